// round 1
// baseline (speedup 1.0000x reference)
#include <cuda_runtime.h>
#include <math.h>

// ---------------- problem constants ----------------
#define N1 4096
#define N2 2048
#define PD 256
#define DZ 128
#define PD2 258
#define FD 772
#define EPSF 1e-12f
#define INV_TEMP 0.08838834764831843f   // 1/sqrt(128)

// ---------------- device scratch (no allocs allowed) ----------------
__device__ float g_k[N1 * DZ];        // k / k2 projections  [4096,128]
__device__ float g_q[N2 * DZ];        // q projection        [2048,128]
__device__ float g_q2[N2 * DZ];       // q2 projection       [2048,128]
__device__ float g_S[(size_t)N2 * N1];// scores / attr       [2048,4096]
__device__ float g_lmf[N1 * PD2];     // lm_feature          [4096,258]
__device__ float g_P[N2 * PD2];       // prop0 / prop1       [2048,258]
__device__ float g_f1[N2 * PD2];      // tg_feature_1
__device__ float g_f2[N2 * PD2];      // tg_feature_2
__device__ float g_router0[PD2];
__device__ float g_routerp[PD2];
__device__ float g_router1[PD2];
__device__ float g_delay[N1];
__device__ float g_dsum;
__device__ float g_rou0[N2];
__device__ float g_rou1[N2];
__device__ float g_asum[N2];          // attr row sums
__device__ float g_v2[N1 * 2];

// ---------------- reductions ----------------
__device__ __forceinline__ float blk_sum(float v, float* red) {
    int t = threadIdx.x;
    red[t] = v; __syncthreads();
    for (int s = blockDim.x >> 1; s > 0; s >>= 1) {
        if (t < s) red[t] += red[t + s];
        __syncthreads();
    }
    float r = red[0]; __syncthreads();
    return r;
}
__device__ __forceinline__ float blk_max(float v, float* red) {
    int t = threadIdx.x;
    red[t] = v; __syncthreads();
    for (int s = blockDim.x >> 1; s > 0; s >>= 1) {
        if (t < s) red[t] = fmaxf(red[t], red[t + s]);
        __syncthreads();
    }
    float r = red[0]; __syncthreads();
    return r;
}

// ---------------- small prep kernels ----------------
__global__ void k_lmfeat(const float* __restrict__ lm_X, const float* __restrict__ lm_Y) {
    int i = blockIdx.x * blockDim.x + threadIdx.x;
    if (i < N1 * PD2) {
        int r = i / PD2, c = i - r * PD2;
        g_lmf[i] = (c < PD) ? lm_X[r * PD + c] : lm_Y[r * 2 + (c - PD)];
    }
}

__global__ void k_colmean() {               // router_0 = mean over rows of lm_feature
    __shared__ float red[256];
    int c = blockIdx.x;
    float s = 0.f;
    for (int r = threadIdx.x; r < N1; r += 256) s += g_lmf[r * PD2 + c];
    s = blk_sum(s, red);
    if (threadIdx.x == 0) g_router0[c] = s * (1.0f / N1);
}

__global__ void k_prep(const float* __restrict__ lm_delay, const float* __restrict__ tg_delay,
                       const float* g1p, const float* g2p, const float* g3p,
                       const float* ap, const float* bp) {
    __shared__ float red[1024];
    float a = ap[0], b = bp[0], g1 = g1p[0], g2 = g2p[0], g3 = g3p[0];
    float local = 0.f;
    for (int i = threadIdx.x; i < N1; i += 1024) {
        float d = expf(-g1 * (a * lm_delay[i] + b));
        g_delay[i] = d;
        local += d;
    }
    local = blk_sum(local, red);
    if (threadIdx.x == 0) g_dsum = local;
    for (int i = threadIdx.x; i < N2; i += 1024) {
        float t = a * tg_delay[i] + b;
        g_rou0[i] = expf(-g2 * t);
        g_rou1[i] = expf(-g3 * t);
    }
}

// ---------------- tiled GEMMs ----------------
#define BM 64
#define BN 64
#define BK 16

// C[M,N] = scale * A[M,K] * B[N,K]^T (+ bias[n])
__global__ void gemm_abt(const float* __restrict__ A, const float* __restrict__ B,
                         const float* __restrict__ bias, float* __restrict__ C,
                         int M, int N, int K, float scale) {
    __shared__ float As[BK][BM + 1];
    __shared__ float Bs[BK][BN + 1];
    int t = threadIdx.x;
    int tx = t & 15, ty = t >> 4;
    int m0 = blockIdx.y * BM, n0 = blockIdx.x * BN;
    float acc[4][4] = {};
    int ktiles = (K + BK - 1) / BK;
    for (int kt = 0; kt < ktiles; kt++) {
        int k0 = kt * BK;
        int kl = t & 15;
#pragma unroll
        for (int p = 0; p < 4; p++) {
            int m = (t >> 4) + 16 * p;
            float v = 0.f;
            if (m0 + m < M && k0 + kl < K) v = A[(size_t)(m0 + m) * K + k0 + kl];
            As[kl][m] = v;
        }
#pragma unroll
        for (int p = 0; p < 4; p++) {
            int n = (t >> 4) + 16 * p;
            float v = 0.f;
            if (n0 + n < N && k0 + kl < K) v = B[(size_t)(n0 + n) * K + k0 + kl];
            Bs[kl][n] = v;
        }
        __syncthreads();
#pragma unroll
        for (int kk = 0; kk < BK; kk++) {
            float a[4], b[4];
#pragma unroll
            for (int i = 0; i < 4; i++) a[i] = As[kk][ty * 4 + i];
#pragma unroll
            for (int j = 0; j < 4; j++) b[j] = Bs[kk][tx * 4 + j];
#pragma unroll
            for (int i = 0; i < 4; i++)
#pragma unroll
                for (int j = 0; j < 4; j++) acc[i][j] += a[i] * b[j];
        }
        __syncthreads();
    }
#pragma unroll
    for (int i = 0; i < 4; i++) {
        int m = m0 + ty * 4 + i;
        if (m >= M) continue;
#pragma unroll
        for (int j = 0; j < 4; j++) {
            int n = n0 + tx * 4 + j;
            if (n >= N) continue;
            float v = acc[i][j] * scale;
            if (bias) v += bias[n];
            C[(size_t)m * N + n] = v;
        }
    }
}

// C[M,N] = A[M,K] * B[K,N]  (B row-major)
__global__ void gemm_ab(const float* __restrict__ A, const float* __restrict__ B,
                        float* __restrict__ C, int M, int N, int K) {
    __shared__ float As[BK][BM + 1];
    __shared__ float Bs[BK][BN + 1];
    int t = threadIdx.x;
    int tx = t & 15, ty = t >> 4;
    int m0 = blockIdx.y * BM, n0 = blockIdx.x * BN;
    float acc[4][4] = {};
    int ktiles = (K + BK - 1) / BK;
    for (int kt = 0; kt < ktiles; kt++) {
        int k0 = kt * BK;
        int kl = t & 15;
#pragma unroll
        for (int p = 0; p < 4; p++) {
            int m = (t >> 4) + 16 * p;
            float v = 0.f;
            if (m0 + m < M && k0 + kl < K) v = A[(size_t)(m0 + m) * K + k0 + kl];
            As[kl][m] = v;
        }
#pragma unroll
        for (int p = 0; p < 4; p++) {
            int k = (t >> 6) + 4 * p;
            int n = t & 63;
            float v = 0.f;
            if (k0 + k < K && n0 + n < N) v = B[(size_t)(k0 + k) * N + n0 + n];
            Bs[k][n] = v;
        }
        __syncthreads();
#pragma unroll
        for (int kk = 0; kk < BK; kk++) {
            float a[4], b[4];
#pragma unroll
            for (int i = 0; i < 4; i++) a[i] = As[kk][ty * 4 + i];
#pragma unroll
            for (int j = 0; j < 4; j++) b[j] = Bs[kk][tx * 4 + j];
#pragma unroll
            for (int i = 0; i < 4; i++)
#pragma unroll
                for (int j = 0; j < 4; j++) acc[i][j] += a[i] * b[j];
        }
        __syncthreads();
    }
#pragma unroll
    for (int i = 0; i < 4; i++) {
        int m = m0 + ty * 4 + i;
        if (m >= M) continue;
#pragma unroll
        for (int j = 0; j < 4; j++) {
            int n = n0 + tx * 4 + j;
            if (n >= N) continue;
            C[(size_t)m * N + n] = acc[i][j];
        }
    }
}

// ---------------- attention 1: attr = exp(softmax(scores)), row sums ----------------
__global__ void k_attr() {
    __shared__ float red[256];
    int r = blockIdx.x;
    float* s = g_S + (size_t)r * N1;
    int t = threadIdx.x;
    float e[16];
    float m = -1e30f;
#pragma unroll
    for (int i = 0; i < 16; i++) { e[i] = s[t + i * 256]; m = fmaxf(m, e[i]); }
    m = blk_max(m, red);
    float z = 0.f;
#pragma unroll
    for (int i = 0; i < 16; i++) { e[i] = expf(e[i] - m); z += e[i]; }
    z = blk_sum(z, red);
    float inv = 1.f / z;
    float rs = 0.f;
#pragma unroll
    for (int i = 0; i < 16; i++) {
        float v = expf(e[i] * inv);
        s[t + i * 256] = v;
        rs += v;
    }
    rs = blk_sum(rs, red);
    if (t == 0) g_asum[r] = rs;
}

// ---------------- propagation elementwise ----------------
__global__ void k_prop0(const float* __restrict__ tg_X) {
    int i = blockIdx.x * blockDim.x + threadIdx.x;
    if (i < N2 * PD2) {
        int r = i / PD2, c = i - r * PD2;
        float num = g_P[i] + (c < PD ? tg_X[r * PD + c] : 0.f) + g_rou0[r] * g_router0[c];
        g_P[i] = num / (1.f + g_asum[r] + g_rou0[r] + EPSF);
    }
}

__global__ void k_routerp() {
    __shared__ float red[256];
    int c = blockIdx.x;
    float s = 0.f;
    for (int r = threadIdx.x; r < N1; r += 256) s += g_delay[r] * g_lmf[r * PD2 + c];
    s = blk_sum(s, red);
    if (threadIdx.x == 0)
        g_routerp[c] = (s + g_router0[c]) / (1.f + g_dsum + EPSF);
}

__global__ void k_router1(const float* __restrict__ w1_w, const float* __restrict__ w1_b) {
    int j = threadIdx.x;
    if (j < PD2) {
        float s = w1_b[j];
        for (int k = 0; k < PD2; k++) s += g_routerp[k] * w1_w[j * PD2 + k];
        g_router1[j] = s;
    }
}

__global__ void k_prop1() {
    int i = blockIdx.x * blockDim.x + threadIdx.x;
    if (i < N2 * PD2) {
        int r = i / PD2, c = i - r * PD2;
        g_P[i] = (g_f1[i] + g_rou1[r] * g_router1[c]) / (1.f + g_rou1[r] + EPSF);
    }
}

// ---------------- final feature assembly (written into d_out) ----------------
__global__ void k_final(const float* __restrict__ tg_X, float* __restrict__ out) {
    int i = blockIdx.x * blockDim.x + threadIdx.x;
    if (i < N2 * FD) {
        int r = i / FD, c = i - r * FD;
        float v;
        if (c < PD)             v = tg_X[r * PD + c];
        else if (c < PD + PD2)  v = g_f1[r * PD2 + (c - PD)];
        else                    v = g_f2[r * PD2 + (c - PD - PD2)];
        out[N2 * 2 + i] = v;
    }
}

__global__ void k_v2(const float* __restrict__ lm_Y,
                     const float* __restrict__ pv_w, const float* __restrict__ pv_b) {
    int i = blockIdx.x * blockDim.x + threadIdx.x;
    if (i < N1) {
        float y0 = lm_Y[2 * i], y1 = lm_Y[2 * i + 1];
        g_v2[2 * i]     = pv_w[0] * y0 + pv_w[1] * y1 + pv_b[0];
        g_v2[2 * i + 1] = pv_w[2] * y0 + pv_w[3] * y1 + pv_b[1];
    }
}

// ---------------- attention 2: fused softmax + @v2 ----------------
__global__ void k_attn2(float* __restrict__ out) {
    __shared__ float red[256];
    int r = blockIdx.x;
    const float* s = g_S + (size_t)r * N1;
    int t = threadIdx.x;
    float e[16];
    float m = -1e30f;
#pragma unroll
    for (int i = 0; i < 16; i++) { e[i] = s[t + i * 256]; m = fmaxf(m, e[i]); }
    m = blk_max(m, red);
    float sw = 0.f, s0 = 0.f, s1 = 0.f;
#pragma unroll
    for (int i = 0; i < 16; i++) {
        int idx = t + i * 256;
        float w = expf(e[i] - m);
        sw += w;
        s0 += w * g_v2[2 * idx];
        s1 += w * g_v2[2 * idx + 1];
    }
    sw = blk_sum(sw, red);
    s0 = blk_sum(s0, red);
    s1 = blk_sum(s1, red);
    if (t == 0) {
        out[2 * r]     = s0 / sw;
        out[2 * r + 1] = s1 / sw;
    }
}

// ---------------- host launch ----------------
static float* sym_addr(const void* s) {
    void* p = nullptr;
    cudaGetSymbolAddress(&p, s);
    return (float*)p;
}

extern "C" void kernel_launch(void* const* d_in, const int* in_sizes, int n_in,
                              void* d_out, int out_size) {
    const float* lm_X    = (const float*)d_in[0];
    const float* lm_Y    = (const float*)d_in[1];
    const float* tg_X    = (const float*)d_in[2];
    // d_in[3] = tg_Y (unused by reference)
    const float* lm_delay= (const float*)d_in[4];
    const float* tg_delay= (const float*)d_in[5];
    const float* aq_w    = (const float*)d_in[6];
    const float* aq_b    = (const float*)d_in[7];
    const float* ak_w    = (const float*)d_in[8];
    const float* ak_b    = (const float*)d_in[9];
    const float* w1_w    = (const float*)d_in[10];
    const float* w1_b    = (const float*)d_in[11];
    const float* w2_w    = (const float*)d_in[12];
    const float* w2_b    = (const float*)d_in[13];
    const float* pq_w    = (const float*)d_in[14];
    const float* pq_b    = (const float*)d_in[15];
    const float* pk_w    = (const float*)d_in[16];
    const float* pk_b    = (const float*)d_in[17];
    const float* pv_w    = (const float*)d_in[18];
    const float* pv_b    = (const float*)d_in[19];
    const float* gamma1  = (const float*)d_in[20];
    const float* gamma2  = (const float*)d_in[21];
    const float* gamma3  = (const float*)d_in[22];
    const float* alpha   = (const float*)d_in[23];
    const float* beta    = (const float*)d_in[24];
    float* out = (float*)d_out;

    float* pk  = sym_addr(g_k);
    float* pq  = sym_addr(g_q);
    float* pq2 = sym_addr(g_q2);
    float* pS  = sym_addr(g_S);
    float* plmf= sym_addr(g_lmf);
    float* pP  = sym_addr(g_P);
    float* pf1 = sym_addr(g_f1);
    float* pf2 = sym_addr(g_f2);

    dim3 blk(256);

    // prep
    k_lmfeat<<<(N1 * PD2 + 255) / 256, blk>>>(lm_X, lm_Y);
    k_colmean<<<PD2, blk>>>();
    k_prep<<<1, 1024>>>(lm_delay, tg_delay, gamma1, gamma2, gamma3, alpha, beta);

    // attention 1 projections + scores
    gemm_abt<<<dim3((DZ + BN - 1) / BN, (N1 + BM - 1) / BM), blk>>>(lm_X, ak_w, ak_b, pk, N1, DZ, PD, 1.f);
    gemm_abt<<<dim3((DZ + BN - 1) / BN, (N2 + BM - 1) / BM), blk>>>(tg_X, aq_w, aq_b, pq, N2, DZ, PD, 1.f);
    gemm_abt<<<dim3((N1 + BN - 1) / BN, (N2 + BM - 1) / BM), blk>>>(pq, pk, nullptr, pS, N2, N1, DZ, INV_TEMP);
    k_attr<<<N2, blk>>>();

    // propagation 0
    gemm_ab<<<dim3((PD2 + BN - 1) / BN, (N2 + BM - 1) / BM), blk>>>(pS, plmf, pP, N2, PD2, N1);
    k_prop0<<<(N2 * PD2 + 255) / 256, blk>>>(tg_X);
    k_routerp<<<PD2, blk>>>();
    k_router1<<<1, PD2>>>(w1_w, w1_b);

    // layer 1 + propagation 1 + layer 2
    gemm_abt<<<dim3((PD2 + BN - 1) / BN, (N2 + BM - 1) / BM), blk>>>(pP, w1_w, w1_b, pf1, N2, PD2, PD2, 1.f);
    k_prop1<<<(N2 * PD2 + 255) / 256, blk>>>();
    gemm_abt<<<dim3((PD2 + BN - 1) / BN, (N2 + BM - 1) / BM), blk>>>(pP, w2_w, w2_b, pf2, N2, PD2, PD2, 1.f);

    // final features -> out, then attention 2
    k_final<<<(N2 * FD + 255) / 256, blk>>>(tg_X, out);
    gemm_abt<<<dim3((DZ + BN - 1) / BN, (N2 + BM - 1) / BM), blk>>>(out + N2 * 2, pq_w, pq_b, pq2, N2, DZ, FD, 1.f);
    gemm_abt<<<dim3((DZ + BN - 1) / BN, (N1 + BM - 1) / BM), blk>>>(lm_X, pk_w, pk_b, pk, N1, DZ, PD, 1.f);
    k_v2<<<(N1 + 255) / 256, blk>>>(lm_Y, pv_w, pv_b);
    gemm_abt<<<dim3((N1 + BN - 1) / BN, (N2 + BM - 1) / BM), blk>>>(pq2, pk, nullptr, pS, N2, N1, DZ, INV_TEMP);
    k_attn2<<<N2, blk>>>(out);
}

// round 2
// speedup vs baseline: 1.4117x; 1.4117x over previous
#include <cuda_runtime.h>
#include <math.h>

// ---------------- problem constants ----------------
#define N1 4096
#define N2 2048
#define PD 256
#define DZ 128
#define PD2 258
#define FD 772
#define EPSF 1e-12f
#define INV_TEMP 0.08838834764831843f   // 1/sqrt(128)

// ---------------- device scratch (no allocs allowed) ----------------
__device__ float g_k[N1 * DZ];
__device__ float g_q[N2 * DZ];
__device__ float g_q2[N2 * DZ];
__device__ float g_S[(size_t)N2 * N1];
__device__ float g_lmf[N1 * PD2];
__device__ float g_P[N2 * PD2];
__device__ float g_f1[N2 * PD2];
__device__ float g_f2[N2 * PD2];
__device__ float g_router0[PD2];
__device__ float g_routerp[PD2];
__device__ float g_router1[PD2];
__device__ float g_delay[N1];
__device__ float g_dsum;
__device__ float g_rou0[N2];
__device__ float g_rou1[N2];
__device__ float g_asum[N2];
__device__ float g_v2[N1 * 2];

// ---------------- reductions ----------------
__device__ __forceinline__ float blk_sum(float v, float* red) {
    int t = threadIdx.x;
    red[t] = v; __syncthreads();
    for (int s = blockDim.x >> 1; s > 0; s >>= 1) {
        if (t < s) red[t] += red[t + s];
        __syncthreads();
    }
    float r = red[0]; __syncthreads();
    return r;
}
__device__ __forceinline__ float blk_max(float v, float* red) {
    int t = threadIdx.x;
    red[t] = v; __syncthreads();
    for (int s = blockDim.x >> 1; s > 0; s >>= 1) {
        if (t < s) red[t] = fmaxf(red[t], red[t + s]);
        __syncthreads();
    }
    float r = red[0]; __syncthreads();
    return r;
}

// ---------------- small prep kernels ----------------
__global__ void k_lmfeat(const float* __restrict__ lm_X, const float* __restrict__ lm_Y) {
    int i = blockIdx.x * blockDim.x + threadIdx.x;
    if (i < N1 * PD2) {
        int r = i / PD2, c = i - r * PD2;
        g_lmf[i] = (c < PD) ? lm_X[r * PD + c] : lm_Y[r * 2 + (c - PD)];
    }
}

__global__ void k_colmean() {
    __shared__ float red[256];
    int c = blockIdx.x;
    float s = 0.f;
    for (int r = threadIdx.x; r < N1; r += 256) s += g_lmf[r * PD2 + c];
    s = blk_sum(s, red);
    if (threadIdx.x == 0) g_router0[c] = s * (1.0f / N1);
}

__global__ void k_prep(const float* __restrict__ lm_delay, const float* __restrict__ tg_delay,
                       const float* g1p, const float* g2p, const float* g3p,
                       const float* ap, const float* bp) {
    __shared__ float red[1024];
    float a = ap[0], b = bp[0], g1 = g1p[0], g2 = g2p[0], g3 = g3p[0];
    float local = 0.f;
    for (int i = threadIdx.x; i < N1; i += 1024) {
        float d = expf(-g1 * (a * lm_delay[i] + b));
        g_delay[i] = d;
        local += d;
    }
    local = blk_sum(local, red);
    if (threadIdx.x == 0) g_dsum = local;
    for (int i = threadIdx.x; i < N2; i += 1024) {
        float t = a * tg_delay[i] + b;
        g_rou0[i] = expf(-g2 * t);
        g_rou1[i] = expf(-g3 * t);
    }
}

// ---------------- tf32 tensor-core GEMM ----------------
// C[M,N] = scale * A[M,K] x op(B) (+ bias[n])
//   BTRANS=true : B given as [N,K] row-major (computes A B^T)
//   BTRANS=false: B given as [K,N] row-major (computes A B)
// Requirements: M % 128 == 0 (true for all call sites). N, K arbitrary.

#define BM 128
#define BN 128
#define BKT 16
#define SPAD 4

__device__ __forceinline__ unsigned f2tf32(float x) {
    unsigned r;
    asm("cvt.rna.tf32.f32 %0, %1;" : "=r"(r) : "f"(x));
    return r;
}

template<bool BTRANS>
__global__ void __launch_bounds__(256)
mma_gemm(const float* __restrict__ A, const float* __restrict__ B,
         const float* __restrict__ bias, float* __restrict__ C,
         int M, int N, int K, float scale)
{
    __shared__ unsigned As[BKT][BM + SPAD];
    __shared__ unsigned Bs[BKT][BN + SPAD];

    const int tid = threadIdx.x;
    const int warp = tid >> 5, lane = tid & 31;
    const int g = lane >> 2, tig = lane & 3;
    const int wm = (warp & 1) * 64;      // warp m-offset in block tile
    const int wn = (warp >> 1) * 32;     // warp n-offset in block tile
    const int m0 = blockIdx.y * BM, n0 = blockIdx.x * BN;

    const bool avec = ((K & 3) == 0);

    float acc[4][4][4];
#pragma unroll
    for (int i = 0; i < 4; i++)
#pragma unroll
        for (int j = 0; j < 4; j++)
#pragma unroll
            for (int c = 0; c < 4; c++) acc[i][j][c] = 0.f;

    const int ktiles = (K + BKT - 1) / BKT;

    float ra[8], rb[8];

    auto loadA = [&](int kt) {
        int k0 = kt * BKT;
        if (avec) {
#pragma unroll
            for (int p = 0; p < 2; p++) {
                int idx = tid + 256 * p;
                int row = idx >> 2, kq = (idx & 3) * 4;
                if (k0 + kq < K) {
                    float4 v = *(const float4*)(A + (size_t)(m0 + row) * K + k0 + kq);
                    ra[p*4+0] = v.x; ra[p*4+1] = v.y; ra[p*4+2] = v.z; ra[p*4+3] = v.w;
                } else {
                    ra[p*4+0] = ra[p*4+1] = ra[p*4+2] = ra[p*4+3] = 0.f;
                }
            }
        } else {
#pragma unroll
            for (int p = 0; p < 8; p++) {
                int idx = tid + 256 * p;
                int row = idx >> 4, kk = idx & 15;
                ra[p] = (k0 + kk < K) ? A[(size_t)(m0 + row) * K + k0 + kk] : 0.f;
            }
        }
    };
    auto storeA = [&]() {
        if (avec) {
#pragma unroll
            for (int p = 0; p < 2; p++) {
                int idx = tid + 256 * p;
                int row = idx >> 2, kq = (idx & 3) * 4;
#pragma unroll
                for (int j = 0; j < 4; j++) As[kq + j][row] = f2tf32(ra[p*4+j]);
            }
        } else {
#pragma unroll
            for (int p = 0; p < 8; p++) {
                int idx = tid + 256 * p;
                int row = idx >> 4, kk = idx & 15;
                As[kk][row] = f2tf32(ra[p]);
            }
        }
    };
    auto loadB = [&](int kt) {
        int k0 = kt * BKT;
        if (BTRANS) {
            if (avec) {
#pragma unroll
                for (int p = 0; p < 2; p++) {
                    int idx = tid + 256 * p;
                    int row = idx >> 2, kq = (idx & 3) * 4;
                    if (n0 + row < N && k0 + kq < K) {
                        float4 v = *(const float4*)(B + (size_t)(n0 + row) * K + k0 + kq);
                        rb[p*4+0] = v.x; rb[p*4+1] = v.y; rb[p*4+2] = v.z; rb[p*4+3] = v.w;
                    } else {
                        rb[p*4+0] = rb[p*4+1] = rb[p*4+2] = rb[p*4+3] = 0.f;
                    }
                }
            } else {
#pragma unroll
                for (int p = 0; p < 8; p++) {
                    int idx = tid + 256 * p;
                    int row = idx >> 4, kk = idx & 15;
                    rb[p] = (n0 + row < N && k0 + kk < K)
                          ? B[(size_t)(n0 + row) * K + k0 + kk] : 0.f;
                }
            }
        } else {
#pragma unroll
            for (int p = 0; p < 8; p++) {
                int idx = tid + 256 * p;
                int kk = idx >> 7, n = idx & 127;
                rb[p] = (n0 + n < N && k0 + kk < K)
                      ? B[(size_t)(k0 + kk) * N + n0 + n] : 0.f;
            }
        }
    };
    auto storeB = [&]() {
        if (BTRANS) {
            if (avec) {
#pragma unroll
                for (int p = 0; p < 2; p++) {
                    int idx = tid + 256 * p;
                    int row = idx >> 2, kq = (idx & 3) * 4;
#pragma unroll
                    for (int j = 0; j < 4; j++) Bs[kq + j][row] = f2tf32(rb[p*4+j]);
                }
            } else {
#pragma unroll
                for (int p = 0; p < 8; p++) {
                    int idx = tid + 256 * p;
                    int row = idx >> 4, kk = idx & 15;
                    Bs[kk][row] = f2tf32(rb[p]);
                }
            }
        } else {
#pragma unroll
            for (int p = 0; p < 8; p++) {
                int idx = tid + 256 * p;
                int kk = idx >> 7, n = idx & 127;
                Bs[kk][n] = f2tf32(rb[p]);
            }
        }
    };

    // prologue
    loadA(0); loadB(0);
    storeA(); storeB();
    __syncthreads();

    for (int kt = 0; kt < ktiles; kt++) {
        if (kt + 1 < ktiles) { loadA(kt + 1); loadB(kt + 1); }

#pragma unroll
        for (int ks = 0; ks < 2; ks++) {
            unsigned af[4][4], bf[4][2];
#pragma unroll
            for (int mi = 0; mi < 4; mi++) {
                int mb = wm + mi * 16;
                af[mi][0] = As[ks*8 + tig    ][mb + g    ];
                af[mi][1] = As[ks*8 + tig    ][mb + g + 8];
                af[mi][2] = As[ks*8 + tig + 4][mb + g    ];
                af[mi][3] = As[ks*8 + tig + 4][mb + g + 8];
            }
#pragma unroll
            for (int ni = 0; ni < 4; ni++) {
                int nb = wn + ni * 8;
                bf[ni][0] = Bs[ks*8 + tig    ][nb + g];
                bf[ni][1] = Bs[ks*8 + tig + 4][nb + g];
            }
#pragma unroll
            for (int mi = 0; mi < 4; mi++)
#pragma unroll
                for (int ni = 0; ni < 4; ni++) {
                    asm volatile(
                        "mma.sync.aligned.m16n8k8.row.col.f32.tf32.tf32.f32 "
                        "{%0,%1,%2,%3}, {%4,%5,%6,%7}, {%8,%9}, {%0,%1,%2,%3};"
                        : "+f"(acc[mi][ni][0]), "+f"(acc[mi][ni][1]),
                          "+f"(acc[mi][ni][2]), "+f"(acc[mi][ni][3])
                        : "r"(af[mi][0]), "r"(af[mi][1]), "r"(af[mi][2]), "r"(af[mi][3]),
                          "r"(bf[ni][0]), "r"(bf[ni][1]));
                }
        }
        __syncthreads();
        if (kt + 1 < ktiles) { storeA(); storeB(); __syncthreads(); }
    }

    // epilogue
#pragma unroll
    for (int mi = 0; mi < 4; mi++) {
        int mrow0 = m0 + wm + mi * 16 + g;
#pragma unroll
        for (int ni = 0; ni < 4; ni++) {
            int ncol = n0 + wn + ni * 8 + 2 * tig;
#pragma unroll
            for (int h = 0; h < 2; h++) {
                int mr = mrow0 + h * 8;
                if (ncol < N) {
                    float bv = bias ? bias[ncol] : 0.f;
                    C[(size_t)mr * N + ncol] = acc[mi][ni][h*2+0] * scale + bv;
                }
                if (ncol + 1 < N) {
                    float bv = bias ? bias[ncol + 1] : 0.f;
                    C[(size_t)mr * N + ncol + 1] = acc[mi][ni][h*2+1] * scale + bv;
                }
            }
        }
    }
}

// ---------------- attention 1: attr = exp(softmax(scores)), row sums ----------------
__global__ void k_attr() {
    __shared__ float red[256];
    int r = blockIdx.x;
    float* s = g_S + (size_t)r * N1;
    int t = threadIdx.x;
    float e[16];
    float m = -1e30f;
#pragma unroll
    for (int i = 0; i < 16; i++) { e[i] = s[t + i * 256]; m = fmaxf(m, e[i]); }
    m = blk_max(m, red);
    float z = 0.f;
#pragma unroll
    for (int i = 0; i < 16; i++) { e[i] = expf(e[i] - m); z += e[i]; }
    z = blk_sum(z, red);
    float inv = 1.f / z;
    float rs = 0.f;
#pragma unroll
    for (int i = 0; i < 16; i++) {
        float v = expf(e[i] * inv);
        s[t + i * 256] = v;
        rs += v;
    }
    rs = blk_sum(rs, red);
    if (t == 0) g_asum[r] = rs;
}

// ---------------- propagation elementwise ----------------
__global__ void k_prop0(const float* __restrict__ tg_X) {
    int i = blockIdx.x * blockDim.x + threadIdx.x;
    if (i < N2 * PD2) {
        int r = i / PD2, c = i - r * PD2;
        float num = g_P[i] + (c < PD ? tg_X[r * PD + c] : 0.f) + g_rou0[r] * g_router0[c];
        g_P[i] = num / (1.f + g_asum[r] + g_rou0[r] + EPSF);
    }
}

__global__ void k_routerp() {
    __shared__ float red[256];
    int c = blockIdx.x;
    float s = 0.f;
    for (int r = threadIdx.x; r < N1; r += 256) s += g_delay[r] * g_lmf[r * PD2 + c];
    s = blk_sum(s, red);
    if (threadIdx.x == 0)
        g_routerp[c] = (s + g_router0[c]) / (1.f + g_dsum + EPSF);
}

__global__ void k_router1(const float* __restrict__ w1_w, const float* __restrict__ w1_b) {
    int j = threadIdx.x;
    if (j < PD2) {
        float s = w1_b[j];
        for (int k = 0; k < PD2; k++) s += g_routerp[k] * w1_w[j * PD2 + k];
        g_router1[j] = s;
    }
}

__global__ void k_prop1() {
    int i = blockIdx.x * blockDim.x + threadIdx.x;
    if (i < N2 * PD2) {
        int r = i / PD2, c = i - r * PD2;
        g_P[i] = (g_f1[i] + g_rou1[r] * g_router1[c]) / (1.f + g_rou1[r] + EPSF);
    }
}

// ---------------- final feature assembly (written into d_out) ----------------
__global__ void k_final(const float* __restrict__ tg_X, float* __restrict__ out) {
    int i = blockIdx.x * blockDim.x + threadIdx.x;
    if (i < N2 * FD) {
        int r = i / FD, c = i - r * FD;
        float v;
        if (c < PD)             v = tg_X[r * PD + c];
        else if (c < PD + PD2)  v = g_f1[r * PD2 + (c - PD)];
        else                    v = g_f2[r * PD2 + (c - PD - PD2)];
        out[N2 * 2 + i] = v;
    }
}

__global__ void k_v2(const float* __restrict__ lm_Y,
                     const float* __restrict__ pv_w, const float* __restrict__ pv_b) {
    int i = blockIdx.x * blockDim.x + threadIdx.x;
    if (i < N1) {
        float y0 = lm_Y[2 * i], y1 = lm_Y[2 * i + 1];
        g_v2[2 * i]     = pv_w[0] * y0 + pv_w[1] * y1 + pv_b[0];
        g_v2[2 * i + 1] = pv_w[2] * y0 + pv_w[3] * y1 + pv_b[1];
    }
}

// ---------------- attention 2: fused softmax + @v2 ----------------
__global__ void k_attn2(float* __restrict__ out) {
    __shared__ float red[256];
    int r = blockIdx.x;
    const float* s = g_S + (size_t)r * N1;
    int t = threadIdx.x;
    float e[16];
    float m = -1e30f;
#pragma unroll
    for (int i = 0; i < 16; i++) { e[i] = s[t + i * 256]; m = fmaxf(m, e[i]); }
    m = blk_max(m, red);
    float sw = 0.f, s0 = 0.f, s1 = 0.f;
#pragma unroll
    for (int i = 0; i < 16; i++) {
        int idx = t + i * 256;
        float w = expf(e[i] - m);
        sw += w;
        s0 += w * g_v2[2 * idx];
        s1 += w * g_v2[2 * idx + 1];
    }
    sw = blk_sum(sw, red);
    s0 = blk_sum(s0, red);
    s1 = blk_sum(s1, red);
    if (t == 0) {
        out[2 * r]     = s0 / sw;
        out[2 * r + 1] = s1 / sw;
    }
}

// ---------------- host launch ----------------
static float* sym_addr(const void* s) {
    void* p = nullptr;
    cudaGetSymbolAddress(&p, s);
    return (float*)p;
}

extern "C" void kernel_launch(void* const* d_in, const int* in_sizes, int n_in,
                              void* d_out, int out_size) {
    const float* lm_X    = (const float*)d_in[0];
    const float* lm_Y    = (const float*)d_in[1];
    const float* tg_X    = (const float*)d_in[2];
    const float* lm_delay= (const float*)d_in[4];
    const float* tg_delay= (const float*)d_in[5];
    const float* aq_w    = (const float*)d_in[6];
    const float* aq_b    = (const float*)d_in[7];
    const float* ak_w    = (const float*)d_in[8];
    const float* ak_b    = (const float*)d_in[9];
    const float* w1_w    = (const float*)d_in[10];
    const float* w1_b    = (const float*)d_in[11];
    const float* w2_w    = (const float*)d_in[12];
    const float* w2_b    = (const float*)d_in[13];
    const float* pq_w    = (const float*)d_in[14];
    const float* pq_b    = (const float*)d_in[15];
    const float* pk_w    = (const float*)d_in[16];
    const float* pk_b    = (const float*)d_in[17];
    const float* pv_w    = (const float*)d_in[18];
    const float* pv_b    = (const float*)d_in[19];
    const float* gamma1  = (const float*)d_in[20];
    const float* gamma2  = (const float*)d_in[21];
    const float* gamma3  = (const float*)d_in[22];
    const float* alpha   = (const float*)d_in[23];
    const float* beta    = (const float*)d_in[24];
    float* out = (float*)d_out;

    float* pk  = sym_addr(g_k);
    float* pq  = sym_addr(g_q);
    float* pq2 = sym_addr(g_q2);
    float* pS  = sym_addr(g_S);
    float* plmf= sym_addr(g_lmf);
    float* pP  = sym_addr(g_P);
    float* pf1 = sym_addr(g_f1);
    float* pf2 = sym_addr(g_f2);

    dim3 blk(256);
    auto grid = [](int M, int N) { return dim3((N + BN - 1) / BN, (M + BM - 1) / BM); };

    // prep
    k_lmfeat<<<(N1 * PD2 + 255) / 256, blk>>>(lm_X, lm_Y);
    k_colmean<<<PD2, blk>>>();
    k_prep<<<1, 1024>>>(lm_delay, tg_delay, gamma1, gamma2, gamma3, alpha, beta);

    // attention 1 projections + scores
    mma_gemm<true><<<grid(N1, DZ), blk>>>(lm_X, ak_w, ak_b, pk, N1, DZ, PD, 1.f);
    mma_gemm<true><<<grid(N2, DZ), blk>>>(tg_X, aq_w, aq_b, pq, N2, DZ, PD, 1.f);
    mma_gemm<true><<<grid(N2, N1), blk>>>(pq, pk, nullptr, pS, N2, N1, DZ, INV_TEMP);
    k_attr<<<N2, blk>>>();

    // propagation 0
    mma_gemm<false><<<grid(N2, PD2), blk>>>(pS, plmf, nullptr, pP, N2, PD2, N1, 1.f);
    k_prop0<<<(N2 * PD2 + 255) / 256, blk>>>(tg_X);
    k_routerp<<<PD2, blk>>>();
    k_router1<<<1, PD2>>>(w1_w, w1_b);

    // layer 1 + propagation 1 + layer 2
    mma_gemm<true><<<grid(N2, PD2), blk>>>(pP, w1_w, w1_b, pf1, N2, PD2, PD2, 1.f);
    k_prop1<<<(N2 * PD2 + 255) / 256, blk>>>();
    mma_gemm<true><<<grid(N2, PD2), blk>>>(pP, w2_w, w2_b, pf2, N2, PD2, PD2, 1.f);

    // final features -> out, then attention 2
    k_final<<<(N2 * FD + 255) / 256, blk>>>(tg_X, out);
    mma_gemm<true><<<grid(N2, DZ), blk>>>(out + N2 * 2, pq_w, pq_b, pq2, N2, DZ, FD, 1.f);
    mma_gemm<true><<<grid(N1, DZ), blk>>>(lm_X, pk_w, pk_b, pk, N1, DZ, PD, 1.f);
    k_v2<<<(N1 + 255) / 256, blk>>>(lm_Y, pv_w, pv_b);
    mma_gemm<true><<<grid(N2, N1), blk>>>(pq2, pk, nullptr, pS, N2, N1, DZ, INV_TEMP);
    k_attn2<<<N2, blk>>>(out);
}

// round 3
// speedup vs baseline: 2.6343x; 1.8661x over previous
#include <cuda_runtime.h>
#include <math.h>

// ---------------- problem constants ----------------
#define N1 4096
#define N2 2048
#define PD 256
#define DZ 128
#define PD2 258
#define FD 772
#define EPSF 1e-12f
#define INV_TEMP 0.08838834764831843f   // 1/sqrt(128)

// ---------------- device scratch ----------------
__device__ float g_k[N1 * DZ];
__device__ float g_q[N2 * DZ];
__device__ float g_q2[N2 * DZ];
__device__ float g_S[(size_t)N2 * N1];
__device__ float g_lmf[N1 * PD2];
__device__ float g_P[N2 * PD2];
__device__ float g_f1[N2 * PD2];
__device__ float g_f2[N2 * PD2];
__device__ float g_part[8 * 2048 * 268];   // split-K partials (max ~8.6MB)
__device__ float g_router0[PD2];
__device__ float g_routerp[PD2];
__device__ float g_router1[PD2];
__device__ float g_delay[N1];
__device__ float g_dsum;
__device__ float g_rou0[N2];
__device__ float g_rou1[N2];
__device__ float g_asum[N2];
__device__ float g_v2[N1 * 2];

// ---------------- helpers ----------------
__device__ __forceinline__ float fexp(float x) {
    float y;
    asm("ex2.approx.f32 %0, %1;" : "=f"(y) : "f"(x * 1.4426950408889634f));
    return y;
}
__device__ __forceinline__ unsigned f2tf32(float x) {
    unsigned r;
    asm("cvt.rna.tf32.f32 %0, %1;" : "=r"(r) : "f"(x));
    return r;
}
__device__ __forceinline__ void cp16(float* dst, const float* src, bool valid) {
    unsigned d = (unsigned)__cvta_generic_to_shared(dst);
    int sz = valid ? 16 : 0;
    asm volatile("cp.async.cg.shared.global [%0], [%1], 16, %2;" :: "r"(d), "l"(src), "r"(sz));
}
__device__ __forceinline__ void cp4(float* dst, const float* src, bool valid) {
    unsigned d = (unsigned)__cvta_generic_to_shared(dst);
    int sz = valid ? 4 : 0;
    asm volatile("cp.async.ca.shared.global [%0], [%1], 4, %2;" :: "r"(d), "l"(src), "r"(sz));
}
__device__ __forceinline__ void cp_commit() {
    asm volatile("cp.async.commit_group;");
}
template<int N_>
__device__ __forceinline__ void cp_wait() {
    asm volatile("cp.async.wait_group %0;" :: "n"(N_));
}

__device__ __forceinline__ float blk_sum(float v, float* red) {
    int t = threadIdx.x;
    red[t] = v; __syncthreads();
    for (int s = blockDim.x >> 1; s > 0; s >>= 1) {
        if (t < s) red[t] += red[t + s];
        __syncthreads();
    }
    float r = red[0]; __syncthreads();
    return r;
}
__device__ __forceinline__ float blk_max(float v, float* red) {
    int t = threadIdx.x;
    red[t] = v; __syncthreads();
    for (int s = blockDim.x >> 1; s > 0; s >>= 1) {
        if (t < s) red[t] = fmaxf(red[t], red[t + s]);
        __syncthreads();
    }
    float r = red[0]; __syncthreads();
    return r;
}

// ---------------- small prep kernels ----------------
__global__ void k_lmfeat(const float* __restrict__ lm_X, const float* __restrict__ lm_Y) {
    int i = blockIdx.x * blockDim.x + threadIdx.x;
    if (i < N1 * PD2) {
        int r = i / PD2, c = i - r * PD2;
        g_lmf[i] = (c < PD) ? lm_X[r * PD + c] : lm_Y[r * 2 + (c - PD)];
    }
}

__global__ void k_colmean() {
    __shared__ float red[256];
    int c = blockIdx.x;
    float s = 0.f;
    for (int r = threadIdx.x; r < N1; r += 256) s += g_lmf[r * PD2 + c];
    s = blk_sum(s, red);
    if (threadIdx.x == 0) g_router0[c] = s * (1.0f / N1);
}

__global__ void k_prep(const float* __restrict__ lm_delay, const float* __restrict__ tg_delay,
                       const float* g1p, const float* g2p, const float* g3p,
                       const float* ap, const float* bp) {
    __shared__ float red[1024];
    float a = ap[0], b = bp[0], g1 = g1p[0], g2 = g2p[0], g3 = g3p[0];
    float local = 0.f;
    for (int i = threadIdx.x; i < N1; i += 1024) {
        float d = fexp(-g1 * (a * lm_delay[i] + b));
        g_delay[i] = d;
        local += d;
    }
    local = blk_sum(local, red);
    if (threadIdx.x == 0) g_dsum = local;
    for (int i = threadIdx.x; i < N2; i += 1024) {
        float t = a * tg_delay[i] + b;
        g_rou0[i] = fexp(-g2 * t);
        g_rou1[i] = fexp(-g3 * t);
    }
}

// ---------------- tf32 tensor-core GEMM, 4-stage cp.async, split-K ----------------
// C[M,N] = scale * A[M,K] x op(B) (+ bias)   (scale/bias only when gridDim.z==1)
//   BTRANS=true : B is [N,K] row-major (A B^T); BTRANS=false: B is [K,N]
//   AVEC16: use 16B cp.async for A (requires K%4==0); B uses 16B only if BTRANS&&AVEC16
// M % 128 == 0 required. gridDim.z = SPLIT; partials -> part[z*M*N + m*N + n].

#define BM 128
#define BN 128
#define BKT 16
#define AST 20      // smem row stride (floats) for A / BTRANS-B
#define BSTN 132    // smem row stride for non-trans B
#define STAGES 4

template<bool BTRANS, bool AVEC16>
__global__ void __launch_bounds__(256)
mma_gemm(const float* __restrict__ A, const float* __restrict__ B,
         const float* __restrict__ bias, float* __restrict__ C,
         int M, int N, int K, float scale)
{
    extern __shared__ float smem_dyn[];
    float* AsB = smem_dyn;                               // STAGES*BM*AST
    float* BsB = smem_dyn + STAGES * BM * AST;

    const int tid = threadIdx.x;
    const int warp = tid >> 5, lane = tid & 31;
    const int g = lane >> 2, tig = lane & 3;
    const int wm = (warp & 1) * 64;
    const int wn = (warp >> 1) * 32;
    const int m0 = blockIdx.y * BM, n0 = blockIdx.x * BN;

    const int KT = (K + BKT - 1) / BKT;
    const int SPLIT = gridDim.z;
    const int KTs = (KT + SPLIT - 1) / SPLIT;
    const int kt0 = blockIdx.z * KTs;
    const int kt1 = min(KT, kt0 + KTs);
    const int nk = kt1 - kt0;

    float acc[4][4][4];
#pragma unroll
    for (int i = 0; i < 4; i++)
#pragma unroll
        for (int j = 0; j < 4; j++)
#pragma unroll
            for (int c = 0; c < 4; c++) acc[i][j][c] = 0.f;

    auto loadStage = [&](int kt, int st) {
        int k0 = kt * BKT;
        float* as = AsB + st * BM * AST;
        if (AVEC16) {
#pragma unroll
            for (int p = 0; p < 2; p++) {
                int c = tid + 256 * p;
                int row = c >> 2, kq = (c & 3) * 4;
                cp16(as + row * AST + kq, A + (size_t)(m0 + row) * K + k0 + kq,
                     (k0 + kq) < K);
            }
        } else {
#pragma unroll
            for (int p = 0; p < 8; p++) {
                int e = tid + 256 * p;
                int row = e >> 4, kk = e & 15;
                cp4(as + row * AST + kk, A + (size_t)(m0 + row) * K + k0 + kk,
                    (k0 + kk) < K);
            }
        }
        if (BTRANS) {
            float* bs = BsB + st * BN * AST;
            if (AVEC16) {
#pragma unroll
                for (int p = 0; p < 2; p++) {
                    int c = tid + 256 * p;
                    int row = c >> 2, kq = (c & 3) * 4;
                    bool v = (n0 + row) < N && (k0 + kq) < K;
                    cp16(bs + row * AST + kq, B + (size_t)(n0 + row) * K + k0 + kq, v);
                }
            } else {
#pragma unroll
                for (int p = 0; p < 8; p++) {
                    int e = tid + 256 * p;
                    int row = e >> 4, kk = e & 15;
                    bool v = (n0 + row) < N && (k0 + kk) < K;
                    cp4(bs + row * AST + kk, B + (size_t)(n0 + row) * K + k0 + kk, v);
                }
            }
        } else {
            float* bs = BsB + st * BKT * BSTN;
#pragma unroll
            for (int p = 0; p < 8; p++) {
                int e = tid + 256 * p;
                int kk = e >> 7, n = e & 127;
                bool v = (k0 + kk) < K && (n0 + n) < N;
                cp4(bs + kk * BSTN + n, B + (size_t)(k0 + kk) * N + n0 + n, v);
            }
        }
        cp_commit();
    };

    // prologue: STAGES-1 groups (possibly empty)
#pragma unroll
    for (int s = 0; s < STAGES - 1; s++) {
        if (s < nk) loadStage(kt0 + s, s);
        else cp_commit();
    }

    for (int i = 0; i < nk; i++) {
        cp_wait<STAGES - 2>();
        __syncthreads();

        int j = i + STAGES - 1;
        if (j < nk) loadStage(kt0 + j, j & (STAGES - 1));
        else cp_commit();

        const int st = i & (STAGES - 1);
        const float* as = AsB + st * BM * AST;
        const float* bsT = BsB + st * BN * AST;
        const float* bsN = BsB + st * BKT * BSTN;

#pragma unroll
        for (int ks = 0; ks < 2; ks++) {
            unsigned af[4][4], bf[4][2];
#pragma unroll
            for (int mi = 0; mi < 4; mi++) {
                const float* pa = as + (wm + mi * 16 + g) * AST + ks * 8 + tig;
                af[mi][0] = f2tf32(pa[0]);
                af[mi][1] = f2tf32(pa[8 * AST]);
                af[mi][2] = f2tf32(pa[4]);
                af[mi][3] = f2tf32(pa[8 * AST + 4]);
            }
#pragma unroll
            for (int ni = 0; ni < 4; ni++) {
                if (BTRANS) {
                    const float* pb = bsT + (wn + ni * 8 + g) * AST + ks * 8 + tig;
                    bf[ni][0] = f2tf32(pb[0]);
                    bf[ni][1] = f2tf32(pb[4]);
                } else {
                    const float* pb = bsN + (ks * 8 + tig) * BSTN + wn + ni * 8 + g;
                    bf[ni][0] = f2tf32(pb[0]);
                    bf[ni][1] = f2tf32(pb[4 * BSTN]);
                }
            }
#pragma unroll
            for (int mi = 0; mi < 4; mi++)
#pragma unroll
                for (int ni = 0; ni < 4; ni++) {
                    asm volatile(
                        "mma.sync.aligned.m16n8k8.row.col.f32.tf32.tf32.f32 "
                        "{%0,%1,%2,%3}, {%4,%5,%6,%7}, {%8,%9}, {%0,%1,%2,%3};"
                        : "+f"(acc[mi][ni][0]), "+f"(acc[mi][ni][1]),
                          "+f"(acc[mi][ni][2]), "+f"(acc[mi][ni][3])
                        : "r"(af[mi][0]), "r"(af[mi][1]), "r"(af[mi][2]), "r"(af[mi][3]),
                          "r"(bf[ni][0]), "r"(bf[ni][1]));
                }
        }
    }

    // epilogue
    const bool split = (gridDim.z > 1);
    float* outp = split ? (C + (size_t)blockIdx.z * M * N) : C;
#pragma unroll
    for (int mi = 0; mi < 4; mi++) {
        int mrow0 = m0 + wm + mi * 16 + g;
#pragma unroll
        for (int ni = 0; ni < 4; ni++) {
            int ncol = n0 + wn + ni * 8 + 2 * tig;
#pragma unroll
            for (int h = 0; h < 2; h++) {
                int mr = mrow0 + h * 8;
                if (split) {
                    if (ncol < N)     outp[(size_t)mr * N + ncol]     = acc[mi][ni][h*2+0];
                    if (ncol + 1 < N) outp[(size_t)mr * N + ncol + 1] = acc[mi][ni][h*2+1];
                } else {
                    if (ncol < N) {
                        float bv = bias ? bias[ncol] : 0.f;
                        outp[(size_t)mr * N + ncol] = acc[mi][ni][h*2+0] * scale + bv;
                    }
                    if (ncol + 1 < N) {
                        float bv = bias ? bias[ncol + 1] : 0.f;
                        outp[(size_t)mr * N + ncol + 1] = acc[mi][ni][h*2+1] * scale + bv;
                    }
                }
            }
        }
    }
}

// deterministic split-K reduce
__global__ void k_reduce(const float* __restrict__ part, const float* __restrict__ bias,
                         float* __restrict__ C, int M, int N, int S, float scale) {
    int i = blockIdx.x * blockDim.x + threadIdx.x;
    if (i < M * N) {
        int n = i % N;
        float s = 0.f;
        for (int z = 0; z < S; z++) s += part[(size_t)z * M * N + i];
        C[i] = s * scale + (bias ? bias[n] : 0.f);
    }
}

// ---------------- attention 1 ----------------
__global__ void k_attr() {
    __shared__ float red[256];
    int r = blockIdx.x;
    float* s = g_S + (size_t)r * N1;
    int t = threadIdx.x;
    float e[16];
    float m = -1e30f;
#pragma unroll
    for (int i = 0; i < 16; i++) { e[i] = s[t + i * 256]; m = fmaxf(m, e[i]); }
    m = blk_max(m, red);
    float z = 0.f;
#pragma unroll
    for (int i = 0; i < 16; i++) { e[i] = fexp(e[i] - m); z += e[i]; }
    z = blk_sum(z, red);
    float inv = 1.f / z;
    float rs = 0.f;
#pragma unroll
    for (int i = 0; i < 16; i++) {
        float v = fexp(e[i] * inv);
        s[t + i * 256] = v;
        rs += v;
    }
    rs = blk_sum(rs, red);
    if (t == 0) g_asum[r] = rs;
}

// ---------------- propagation elementwise ----------------
__global__ void k_prop0(const float* __restrict__ tg_X) {
    int i = blockIdx.x * blockDim.x + threadIdx.x;
    if (i < N2 * PD2) {
        int r = i / PD2, c = i - r * PD2;
        float num = g_P[i] + (c < PD ? tg_X[r * PD + c] : 0.f) + g_rou0[r] * g_router0[c];
        g_P[i] = num / (1.f + g_asum[r] + g_rou0[r] + EPSF);
    }
}

__global__ void k_routerp() {
    __shared__ float red[256];
    int c = blockIdx.x;
    float s = 0.f;
    for (int r = threadIdx.x; r < N1; r += 256) s += g_delay[r] * g_lmf[r * PD2 + c];
    s = blk_sum(s, red);
    if (threadIdx.x == 0)
        g_routerp[c] = (s + g_router0[c]) / (1.f + g_dsum + EPSF);
}

__global__ void k_router1(const float* __restrict__ w1_w, const float* __restrict__ w1_b) {
    int j = threadIdx.x;
    if (j < PD2) {
        float s = w1_b[j];
        for (int k = 0; k < PD2; k++) s += g_routerp[k] * w1_w[j * PD2 + k];
        g_router1[j] = s;
    }
}

__global__ void k_prop1() {
    int i = blockIdx.x * blockDim.x + threadIdx.x;
    if (i < N2 * PD2) {
        int r = i / PD2, c = i - r * PD2;
        g_P[i] = (g_f1[i] + g_rou1[r] * g_router1[c]) / (1.f + g_rou1[r] + EPSF);
    }
}

__global__ void k_final(const float* __restrict__ tg_X, float* __restrict__ out) {
    int i = blockIdx.x * blockDim.x + threadIdx.x;
    if (i < N2 * FD) {
        int r = i / FD, c = i - r * FD;
        float v;
        if (c < PD)             v = tg_X[r * PD + c];
        else if (c < PD + PD2)  v = g_f1[r * PD2 + (c - PD)];
        else                    v = g_f2[r * PD2 + (c - PD - PD2)];
        out[N2 * 2 + i] = v;
    }
}

__global__ void k_v2(const float* __restrict__ lm_Y,
                     const float* __restrict__ pv_w, const float* __restrict__ pv_b) {
    int i = blockIdx.x * blockDim.x + threadIdx.x;
    if (i < N1) {
        float y0 = lm_Y[2 * i], y1 = lm_Y[2 * i + 1];
        g_v2[2 * i]     = pv_w[0] * y0 + pv_w[1] * y1 + pv_b[0];
        g_v2[2 * i + 1] = pv_w[2] * y0 + pv_w[3] * y1 + pv_b[1];
    }
}

__global__ void k_attn2(float* __restrict__ out) {
    __shared__ float red[256];
    int r = blockIdx.x;
    const float* s = g_S + (size_t)r * N1;
    int t = threadIdx.x;
    float e[16];
    float m = -1e30f;
#pragma unroll
    for (int i = 0; i < 16; i++) { e[i] = s[t + i * 256]; m = fmaxf(m, e[i]); }
    m = blk_max(m, red);
    float sw = 0.f, s0 = 0.f, s1 = 0.f;
#pragma unroll
    for (int i = 0; i < 16; i++) {
        int idx = t + i * 256;
        float w = fexp(e[i] - m);
        sw += w;
        s0 += w * g_v2[2 * idx];
        s1 += w * g_v2[2 * idx + 1];
    }
    sw = blk_sum(sw, red);
    s0 = blk_sum(s0, red);
    s1 = blk_sum(s1, red);
    if (t == 0) {
        out[2 * r]     = s0 / sw;
        out[2 * r + 1] = s1 / sw;
    }
}

// ---------------- host launch ----------------
static float* sym_addr(const void* s) {
    void* p = nullptr;
    cudaGetSymbolAddress(&p, s);
    return (float*)p;
}

#define SMEM_TT ((STAGES * BM * AST + STAGES * BN * AST) * 4)
#define SMEM_FF ((STAGES * BM * AST + STAGES * BKT * BSTN) * 4)

extern "C" void kernel_launch(void* const* d_in, const int* in_sizes, int n_in,
                              void* d_out, int out_size) {
    const float* lm_X    = (const float*)d_in[0];
    const float* lm_Y    = (const float*)d_in[1];
    const float* tg_X    = (const float*)d_in[2];
    const float* lm_delay= (const float*)d_in[4];
    const float* tg_delay= (const float*)d_in[5];
    const float* aq_w    = (const float*)d_in[6];
    const float* aq_b    = (const float*)d_in[7];
    const float* ak_w    = (const float*)d_in[8];
    const float* ak_b    = (const float*)d_in[9];
    const float* w1_w    = (const float*)d_in[10];
    const float* w1_b    = (const float*)d_in[11];
    const float* w2_w    = (const float*)d_in[12];
    const float* w2_b    = (const float*)d_in[13];
    const float* pq_w    = (const float*)d_in[14];
    const float* pq_b    = (const float*)d_in[15];
    const float* pk_w    = (const float*)d_in[16];
    const float* pk_b    = (const float*)d_in[17];
    const float* pv_w    = (const float*)d_in[18];
    const float* pv_b    = (const float*)d_in[19];
    const float* gamma1  = (const float*)d_in[20];
    const float* gamma2  = (const float*)d_in[21];
    const float* gamma3  = (const float*)d_in[22];
    const float* alpha   = (const float*)d_in[23];
    const float* beta    = (const float*)d_in[24];
    float* out = (float*)d_out;

    float* pk   = sym_addr(g_k);
    float* pq   = sym_addr(g_q);
    float* pq2  = sym_addr(g_q2);
    float* pS   = sym_addr(g_S);
    float* plmf = sym_addr(g_lmf);
    float* pP   = sym_addr(g_P);
    float* pf1  = sym_addr(g_f1);
    float* pf2  = sym_addr(g_f2);
    float* pPart= sym_addr(g_part);

    cudaFuncSetAttribute(mma_gemm<true, true>,  cudaFuncAttributeMaxDynamicSharedMemorySize, SMEM_TT);
    cudaFuncSetAttribute(mma_gemm<true, false>, cudaFuncAttributeMaxDynamicSharedMemorySize, SMEM_TT);
    cudaFuncSetAttribute(mma_gemm<false, true>, cudaFuncAttributeMaxDynamicSharedMemorySize, SMEM_FF);

    dim3 blk(256);
    auto grd = [](int M, int N, int S) {
        return dim3((N + BN - 1) / BN, (M + BM - 1) / BM, S);
    };
    auto redu = [&](float* dst, const float* bias, int M, int N, int S, float scale) {
        k_reduce<<<(M * N + 255) / 256, blk>>>(pPart, bias, dst, M, N, S, scale);
    };

    // prep
    k_lmfeat<<<(N1 * PD2 + 255) / 256, blk>>>(lm_X, lm_Y);
    k_colmean<<<PD2, blk>>>();
    k_prep<<<1, 1024>>>(lm_delay, tg_delay, gamma1, gamma2, gamma3, alpha, beta);

    // attention 1: projections (split-K) + scores
    mma_gemm<true, true><<<grd(N1, DZ, 4), blk, SMEM_TT>>>(lm_X, ak_w, nullptr, pPart, N1, DZ, PD, 1.f);
    redu(pk, ak_b, N1, DZ, 4, 1.f);
    mma_gemm<true, true><<<grd(N2, DZ, 8), blk, SMEM_TT>>>(tg_X, aq_w, nullptr, pPart, N2, DZ, PD, 1.f);
    redu(pq, aq_b, N2, DZ, 8, 1.f);
    mma_gemm<true, true><<<grd(N2, N1, 1), blk, SMEM_TT>>>(pq, pk, nullptr, pS, N2, N1, DZ, INV_TEMP);
    k_attr<<<N2, blk>>>();

    // propagation 0: attr @ lm_feature (non-trans B, K=4096), split-K 4
    mma_gemm<false, true><<<grd(N2, PD2, 4), blk, SMEM_FF>>>(pS, plmf, nullptr, pPart, N2, PD2, N1, 1.f);
    redu(pP, nullptr, N2, PD2, 4, 1.f);
    k_prop0<<<(N2 * PD2 + 255) / 256, blk>>>(tg_X);
    k_routerp<<<PD2, blk>>>();
    k_router1<<<1, PD2>>>(w1_w, w1_b);

    // layer 1 + propagation 1 + layer 2 (K=258 -> 4B path)
    mma_gemm<true, false><<<grd(N2, PD2, 4), blk, SMEM_TT>>>(pP, w1_w, nullptr, pPart, N2, PD2, PD2, 1.f);
    redu(pf1, w1_b, N2, PD2, 4, 1.f);
    k_prop1<<<(N2 * PD2 + 255) / 256, blk>>>();
    mma_gemm<true, false><<<grd(N2, PD2, 4), blk, SMEM_TT>>>(pP, w2_w, nullptr, pPart, N2, PD2, PD2, 1.f);
    redu(pf2, w2_b, N2, PD2, 4, 1.f);

    // final features -> out, then attention 2
    k_final<<<(N2 * FD + 255) / 256, blk>>>(tg_X, out);
    mma_gemm<true, true><<<grd(N2, DZ, 8), blk, SMEM_TT>>>(out + N2 * 2, pq_w, nullptr, pPart, N2, DZ, FD, 1.f);
    redu(pq2, pq_b, N2, DZ, 8, 1.f);
    mma_gemm<true, true><<<grd(N1, DZ, 4), blk, SMEM_TT>>>(lm_X, pk_w, nullptr, pPart, N1, DZ, PD, 1.f);
    redu(pk, pk_b, N1, DZ, 4, 1.f);
    k_v2<<<(N1 + 255) / 256, blk>>>(lm_Y, pv_w, pv_b);
    mma_gemm<true, true><<<grd(N2, N1, 1), blk, SMEM_TT>>>(pq2, pk, nullptr, pS, N2, N1, DZ, INV_TEMP);
    k_attn2<<<N2, blk>>>(out);
}